// round 5
// baseline (speedup 1.0000x reference)
#include <cuda_runtime.h>

// ---------------- problem constants ----------------
#define NSEQ  704          // B*F = 8*88
#define TT    512
#define CDIM  64
#define HDIM  64
#define GDIM  192          // 3*H
#define MROWS (NSEQ*TT)    // 360448
#define SPC   5            // sequences per recur CTA
#define NCTA_R ((NSEQ + SPC - 1) / SPC)   // 141

// ---------------- scratch (device globals; no allocation) ----------------
__device__ float g_pre[(size_t)2 * MROWS * GDIM];   // [dir][row][192]
__device__ float g_hbuf[(size_t)MROWS * 2 * HDIM];  // [row][128]

typedef unsigned long long u64;

__device__ __forceinline__ u64 fma2(u64 a, u64 b, u64 c) {
    u64 d;
    asm("fma.rn.f32x2 %0, %1, %2, %3;" : "=l"(d) : "l"(a), "l"(b), "l"(c));
    return d;
}
__device__ __forceinline__ float2 u2f(u64 v) {
    float2 r;
    asm("mov.b64 {%0,%1}, %2;" : "=f"(r.x), "=f"(r.y) : "l"(v));
    return r;
}
__device__ __forceinline__ float tanh_fast(float x) {
    float y;
    asm("tanh.approx.f32 %0, %1;" : "=f"(y) : "f"(x));
    return y;
}
__device__ __forceinline__ float sig_fast(float x) {
    return 0.5f * tanh_fast(0.5f * x) + 0.5f;
}
__device__ __forceinline__ float sig_acc(float x) {
    return __fdividef(1.f, 1.f + __expf(-x));
}

// ---------------- input-projection GEMM ----------------
// CTA tile: 64 rows x 192 cols. Thread tile: 4 rows x 16 cols (8 f32x2).
// acc = 64 regs -> no spills; occupancy 3 hides fill/sync phases.
template<int KD>
__global__ __launch_bounds__(192, 3)
void proj_kernel(const float* __restrict__ xin,
                 const float* __restrict__ W,     // [2][192][KD]
                 const float* __restrict__ bias)  // [2][192]
{
    const float* in = (KD == CDIM) ? xin : (const float*)g_hbuf;
    const int d    = blockIdx.y;
    const int row0 = blockIdx.x * 64;
    const int tid  = threadIdx.x;
    const int tx   = tid % 12;   // 16 output cols each
    const int ty   = tid / 12;   // 4 rows each

    __shared__ float2 xs[16 * 64];    // [k][m] duplicated pairs (8 KB)
    __shared__ float  ws[16 * 192];   // [k][n] transposed       (12 KB)

    u64 acc[4][8];
#pragma unroll
    for (int m = 0; m < 4; m++)
#pragma unroll
        for (int p = 0; p < 8; p++) acc[m][p] = 0ull;

    const float* Wd = W + (size_t)d * GDIM * KD;

    for (int kc = 0; kc < KD / 16; kc++) {
        __syncthreads();
        // x chunk: transpose + duplicate into lanes (64 rows x 16 k)
        for (int i = tid; i < 256; i += 192) {
            int m = i >> 2, kk = (i & 3) * 4;
            float4 v = *(const float4*)(in + (size_t)(row0 + m) * KD + kc * 16 + kk);
            xs[(kk + 0) * 64 + m] = make_float2(v.x, v.x);
            xs[(kk + 1) * 64 + m] = make_float2(v.y, v.y);
            xs[(kk + 2) * 64 + m] = make_float2(v.z, v.z);
            xs[(kk + 3) * 64 + m] = make_float2(v.w, v.w);
        }
        // W chunk: transpose so adjacent cols are adjacent in memory
        for (int i = tid; i < 768; i += 192) {
            int n = i >> 2, kk = (i & 3) * 4;
            float4 v = *(const float4*)(Wd + (size_t)n * KD + kc * 16 + kk);
            ws[(kk + 0) * 192 + n] = v.x;
            ws[(kk + 1) * 192 + n] = v.y;
            ws[(kk + 2) * 192 + n] = v.z;
            ws[(kk + 3) * 192 + n] = v.w;
        }
        __syncthreads();

#pragma unroll
        for (int k = 0; k < 16; k++) {
            const ulonglong2* xp = (const ulonglong2*)(xs + k * 64 + ty * 4);
            const ulonglong2* wp = (const ulonglong2*)(ws + k * 192 + tx * 16);
            ulonglong2 xa = xp[0], xb = xp[1];
            ulonglong2 wa = wp[0], wb = wp[1], wc = wp[2], wd2 = wp[3];
            u64 xv[4] = {xa.x, xa.y, xb.x, xb.y};
            u64 wv[8] = {wa.x, wa.y, wb.x, wb.y, wc.x, wc.y, wd2.x, wd2.y};
#pragma unroll
            for (int m = 0; m < 4; m++)
#pragma unroll
                for (int p = 0; p < 8; p++)
                    acc[m][p] = fma2(xv[m], wv[p], acc[m][p]);
        }
    }

    float2 b2[8];
#pragma unroll
    for (int p = 0; p < 8; p++)
        b2[p] = *(const float2*)(bias + d * GDIM + tx * 16 + 2 * p);

#pragma unroll
    for (int m = 0; m < 4; m++) {
        size_t row = (size_t)row0 + ty * 4 + m;
        float4* op = (float4*)(g_pre + ((size_t)d * MROWS + row) * GDIM + tx * 16);
#pragma unroll
        for (int q = 0; q < 4; q++) {
            float2 va = u2f(acc[m][2 * q]);
            float2 vb = u2f(acc[m][2 * q + 1]);
            op[q] = make_float4(va.x + b2[2 * q].x,     va.y + b2[2 * q].y,
                                vb.x + b2[2 * q + 1].x, vb.y + b2[2 * q + 1].y);
        }
    }
}

// ---------------- recurrence: 5 sequences per CTA (unchanged) ----------------
__global__ __launch_bounds__(192, 2)
void recur_kernel(const float* __restrict__ Whh,   // [2][192][64]
                  const float* __restrict__ bhh)   // [2][192]
{
    const int d   = blockIdx.y;
    const int n0  = blockIdx.x * SPC;
    const int tid = threadIdx.x;

    __shared__ float h_sh[SPC][64];
    __shared__ float s_v[SPC][256];

    u64 w2[32];
    const u64* wr = (const u64*)(Whh + ((size_t)d * GDIM + tid) * HDIM);
#pragma unroll
    for (int q = 0; q < 32; q++) w2[q] = wr[q];
    const float bh = bhh[d * GDIM + tid];

    for (int i = tid; i < SPC * 64; i += 192) ((float*)h_sh)[i] = 0.f;
    __syncthreads();

    const int t0  = d ? (TT - 1) : 0;
    const int dt  = d ? -1 : 1;
    const long dtG = (long)dt * GDIM;

    const float* pcur[SPC];
#pragma unroll
    for (int s = 0; s < SPC; s++) {
        int n = n0 + s;
        int nc = (n < NSEQ) ? n : 0;
        pcur[s] = g_pre + ((size_t)d * MROWS + (size_t)nc * TT + t0) * GDIM + tid;
    }

    const int sA0 = tid / 64;           // 0..2
    const int iA  = tid % 64;
    const int sA1 = sA0 + 3;            // 3..5
    const bool vA0 = (n0 + sA0) < NSEQ;
    const bool vA1 = (sA1 < SPC) && ((n0 + sA1) < NSEQ);
    float* hp0 = g_hbuf + ((size_t)(n0 + sA0) * TT + t0) * 128 + d * 64 + iA;
    float* hp1 = vA1 ? (g_hbuf + ((size_t)(n0 + sA1) * TT + t0) * 128 + d * 64 + iA) : hp0;
    const long dtH = (long)dt * 128;

    float pc[SPC];
#pragma unroll
    for (int s = 0; s < SPC; s++) { pc[s] = __ldg(pcur[s]); pcur[s] += dtG; }

    for (int step = 0; step < TT; step++) {
        float pn[SPC];
        if (step < TT - 1) {
#pragma unroll
            for (int s = 0; s < SPC; s++) { pn[s] = __ldg(pcur[s]); pcur[s] += dtG; }
        }

#pragma unroll
        for (int s = 0; s < SPC; s++) {
            u64 a0 = 0, a1 = 0, a2 = 0, a3 = 0;
            const ulonglong2* h2 = (const ulonglong2*)h_sh[s];
#pragma unroll
            for (int q = 0; q < 16; q += 2) {
                ulonglong2 hv = h2[q];
                ulonglong2 hw = h2[q + 1];
                a0 = fma2(w2[2 * q + 0], hv.x, a0);
                a1 = fma2(w2[2 * q + 1], hv.y, a1);
                a2 = fma2(w2[2 * q + 2], hw.x, a2);
                a3 = fma2(w2[2 * q + 3], hw.y, a3);
            }
            float2 f0 = u2f(a0), f1 = u2f(a1), f2_ = u2f(a2), f3 = u2f(a3);
            float hh = ((f0.x + f0.y) + (f1.x + f1.y)) +
                       ((f2_.x + f2_.y) + (f3.x + f3.y)) + bh;
            if (tid < 128) {
                s_v[s][tid] = hh + pc[s];        // r, z pre-activations
            } else {
                s_v[s][tid]      = hh;           // hn
                s_v[s][tid + 64] = pc[s];        // pn
            }
        }
        __syncthreads();

        {
            const float* sv = s_v[sA0];
            float r    = sig_fast(sv[iA]);
            float z    = sig_fast(sv[64 + iA]);
            float nn   = tanh_fast(sv[192 + iA] + r * sv[128 + iA]);
            float hold = h_sh[sA0][iA];
            float hnew = nn + z * (hold - nn);
            h_sh[sA0][iA] = hnew;
            if (vA0) *hp0 = hnew;
            hp0 += dtH;
        }
        if (sA1 < SPC) {
            const float* sv = s_v[sA1];
            float r    = sig_fast(sv[iA]);
            float z    = sig_fast(sv[64 + iA]);
            float nn   = tanh_fast(sv[192 + iA] + r * sv[128 + iA]);
            float hold = h_sh[sA1][iA];
            float hnew = nn + z * (hold - nn);
            h_sh[sA1][iA] = hnew;
            if (vA1) *hp1 = hnew;
            hp1 += dtH;
        }
        __syncthreads();

#pragma unroll
        for (int s = 0; s < SPC; s++) pc[s] = pn[s];
    }
}

// ---------------- FC head ----------------
__global__ void fc_kernel(const float* __restrict__ fcw,
                          const float* __restrict__ fcb,
                          float* __restrict__ out)
{
    int g    = blockIdx.x * 8 + (threadIdx.x >> 5);
    int lane = threadIdx.x & 31;
    if (g >= MROWS) return;
    float4 v = *(const float4*)(g_hbuf + (size_t)g * 128 + lane * 4);
    float4 w = *(const float4*)(fcw + lane * 4);
    float dot = v.x * w.x + v.y * w.y + v.z * w.z + v.w * w.w;
#pragma unroll
    for (int o = 16; o > 0; o >>= 1) dot += __shfl_down_sync(0xffffffffu, dot, o);
    if (lane == 0) {
        int nidx = g / TT, t = g % TT;
        int b = nidx / 88, f = nidx % 88;
        out[((size_t)b * TT + t) * 88 + f] = sig_acc(dot + fcb[0]);
    }
}

// ---------------- launch ----------------
extern "C" void kernel_launch(void* const* d_in, const int* in_sizes, int n_in,
                              void* d_out, int out_size)
{
    const float* x    = (const float*)d_in[0];
    const float* Wih0 = (const float*)d_in[1];
    const float* Whh0 = (const float*)d_in[2];
    const float* bih0 = (const float*)d_in[3];
    const float* bhh0 = (const float*)d_in[4];
    const float* Wih1 = (const float*)d_in[5];
    const float* Whh1 = (const float*)d_in[6];
    const float* bih1 = (const float*)d_in[7];
    const float* bhh1 = (const float*)d_in[8];
    const float* fcw  = (const float*)d_in[9];
    const float* fcb  = (const float*)d_in[10];
    float* out = (float*)d_out;

    dim3 pg(MROWS / 64, 2);
    dim3 rg(NCTA_R, 2);

    proj_kernel<CDIM><<<pg, 192>>>(x, Wih0, bih0);
    recur_kernel<<<rg, 192>>>(Whh0, bhh0);
    proj_kernel<2 * HDIM><<<pg, 192>>>(x, Wih1, bih1);
    recur_kernel<<<rg, 192>>>(Whh1, bhh1);
    fc_kernel<<<MROWS / 8, 256>>>(fcw, fcb, out);
}

// round 6
// speedup vs baseline: 1.5863x; 1.5863x over previous
#include <cuda_runtime.h>

// ---------------- problem constants ----------------
#define NSEQ  704          // B*F = 8*88
#define TT    512
#define CDIM  64
#define HDIM  64
#define GDIM  192          // 3*H
#define MROWS (NSEQ*TT)    // 360448
#define SPC   5            // sequences per recur CTA
#define NCTA_R ((NSEQ + SPC - 1) / SPC)   // 141

// ---------------- scratch (device globals; no allocation) ----------------
__device__ float g_pre[(size_t)2 * MROWS * GDIM];   // [dir][row][192]
__device__ float g_hbuf[(size_t)MROWS * 2 * HDIM];  // [row][128]

typedef unsigned long long u64;

__device__ __forceinline__ u64 fma2(u64 a, u64 b, u64 c) {
    u64 d;
    asm("fma.rn.f32x2 %0, %1, %2, %3;" : "=l"(d) : "l"(a), "l"(b), "l"(c));
    return d;
}
__device__ __forceinline__ float2 u2f(u64 v) {
    float2 r;
    asm("mov.b64 {%0,%1}, %2;" : "=f"(r.x), "=f"(r.y) : "l"(v));
    return r;
}
__device__ __forceinline__ float tanh_fast(float x) {
    float y;
    asm("tanh.approx.f32 %0, %1;" : "=f"(y) : "f"(x));
    return y;
}
__device__ __forceinline__ float sig_fast(float x) {
    return 0.5f * tanh_fast(0.5f * x) + 0.5f;
}
__device__ __forceinline__ float sig_acc(float x) {
    return __fdividef(1.f, 1.f + __expf(-x));
}

// ---------------- input-projection: W-rows-in-registers, x broadcast ----------------
// One CTA = 384 threads = 384 gate rows (192 gates x 2 dirs; W is [2*192][KD]
// contiguous). Each thread keeps its full W row in registers. x rows stream
// through a double-buffered smem tile; every thread reads each x row via
// broadcast LDS (uniform address). Per row: KD/4 LDS.128 + KD/2 FMA2 —
// LDS structural floor and FMA2 pipe are exactly balanced.
template<int KD>
__global__ __launch_bounds__(384)
void proj_kernel(const float* __restrict__ xin,
                 const float* __restrict__ W,     // [2][192][KD] = [384][KD]
                 const float* __restrict__ bias)  // [2][192]    = [384]
{
    const float* in = (KD == CDIM) ? xin : (const float*)g_hbuf;
    const int tid  = threadIdx.x;          // 0..383
    const int row0 = blockIdx.x * 256;     // 256 rows per CTA, 8 chunks of 32

    __shared__ __align__(16) float xs[2][32 * KD];

    // full W row in registers
    u64 w[KD / 2];
    const u64* wr = (const u64*)(W + (size_t)tid * KD);
#pragma unroll
    for (int q = 0; q < KD / 2; q++) w[q] = wr[q];
    const float b = bias[tid];

    const int d = tid / 192;
    const int g = tid % 192;
    float* outp = g_pre + ((size_t)d * MROWS + row0) * GDIM + g;

    // chunk 0 load
    {
        const float4* s4 = (const float4*)(in + (size_t)row0 * KD);
        float4* dst = (float4*)xs[0];
        for (int i = tid; i < 32 * KD / 4; i += 384) dst[i] = s4[i];
    }
    __syncthreads();

#pragma unroll 1
    for (int c = 0; c < 8; c++) {
        const int buf = c & 1;
        if (c < 7) {
            const float4* s4 = (const float4*)(in + (size_t)(row0 + (c + 1) * 32) * KD);
            float4* dst = (float4*)xs[buf ^ 1];
            for (int i = tid; i < 32 * KD / 4; i += 384) dst[i] = s4[i];
        }

#pragma unroll 1
        for (int r = 0; r < 32; r++) {
            const ulonglong2* x2 = (const ulonglong2*)(xs[buf] + r * KD);
            u64 a0 = 0, a1 = 0, a2 = 0, a3 = 0;
#pragma unroll
            for (int q = 0; q < KD / 4; q += 2) {
                ulonglong2 va = x2[q];
                ulonglong2 vb = x2[q + 1];
                a0 = fma2(w[2 * q + 0], va.x, a0);
                a1 = fma2(w[2 * q + 1], va.y, a1);
                a2 = fma2(w[2 * q + 2], vb.x, a2);
                a3 = fma2(w[2 * q + 3], vb.y, a3);
            }
            float2 f0 = u2f(a0), f1 = u2f(a1), f2_ = u2f(a2), f3 = u2f(a3);
            float v = ((f0.x + f0.y) + (f1.x + f1.y)) +
                      ((f2_.x + f2_.y) + (f3.x + f3.y)) + b;
            outp[(size_t)(c * 32 + r) * GDIM] = v;
        }
        __syncthreads();
    }
}

// ---------------- recurrence: 5 sequences per CTA (unchanged from R3 best) ----------------
__global__ __launch_bounds__(192, 2)
void recur_kernel(const float* __restrict__ Whh,   // [2][192][64]
                  const float* __restrict__ bhh)   // [2][192]
{
    const int d   = blockIdx.y;
    const int n0  = blockIdx.x * SPC;
    const int tid = threadIdx.x;

    __shared__ float h_sh[SPC][64];
    __shared__ float s_v[SPC][256];

    u64 w2[32];
    const u64* wr = (const u64*)(Whh + ((size_t)d * GDIM + tid) * HDIM);
#pragma unroll
    for (int q = 0; q < 32; q++) w2[q] = wr[q];
    const float bh = bhh[d * GDIM + tid];

    for (int i = tid; i < SPC * 64; i += 192) ((float*)h_sh)[i] = 0.f;
    __syncthreads();

    const int t0  = d ? (TT - 1) : 0;
    const int dt  = d ? -1 : 1;
    const long dtG = (long)dt * GDIM;

    const float* pcur[SPC];
#pragma unroll
    for (int s = 0; s < SPC; s++) {
        int n = n0 + s;
        int nc = (n < NSEQ) ? n : 0;
        pcur[s] = g_pre + ((size_t)d * MROWS + (size_t)nc * TT + t0) * GDIM + tid;
    }

    const int sA0 = tid / 64;           // 0..2
    const int iA  = tid % 64;
    const int sA1 = sA0 + 3;            // 3..5
    const bool vA0 = (n0 + sA0) < NSEQ;
    const bool vA1 = (sA1 < SPC) && ((n0 + sA1) < NSEQ);
    float* hp0 = g_hbuf + ((size_t)(n0 + sA0) * TT + t0) * 128 + d * 64 + iA;
    float* hp1 = vA1 ? (g_hbuf + ((size_t)(n0 + sA1) * TT + t0) * 128 + d * 64 + iA) : hp0;
    const long dtH = (long)dt * 128;

    float pc[SPC];
#pragma unroll
    for (int s = 0; s < SPC; s++) { pc[s] = __ldg(pcur[s]); pcur[s] += dtG; }

    for (int step = 0; step < TT; step++) {
        float pn[SPC];
        if (step < TT - 1) {
#pragma unroll
            for (int s = 0; s < SPC; s++) { pn[s] = __ldg(pcur[s]); pcur[s] += dtG; }
        }

#pragma unroll
        for (int s = 0; s < SPC; s++) {
            u64 a0 = 0, a1 = 0, a2 = 0, a3 = 0;
            const ulonglong2* h2 = (const ulonglong2*)h_sh[s];
#pragma unroll
            for (int q = 0; q < 16; q += 2) {
                ulonglong2 hv = h2[q];
                ulonglong2 hw = h2[q + 1];
                a0 = fma2(w2[2 * q + 0], hv.x, a0);
                a1 = fma2(w2[2 * q + 1], hv.y, a1);
                a2 = fma2(w2[2 * q + 2], hw.x, a2);
                a3 = fma2(w2[2 * q + 3], hw.y, a3);
            }
            float2 f0 = u2f(a0), f1 = u2f(a1), f2_ = u2f(a2), f3 = u2f(a3);
            float hh = ((f0.x + f0.y) + (f1.x + f1.y)) +
                       ((f2_.x + f2_.y) + (f3.x + f3.y)) + bh;
            if (tid < 128) {
                s_v[s][tid] = hh + pc[s];        // r, z pre-activations
            } else {
                s_v[s][tid]      = hh;           // hn
                s_v[s][tid + 64] = pc[s];        // pn
            }
        }
        __syncthreads();

        {
            const float* sv = s_v[sA0];
            float r    = sig_fast(sv[iA]);
            float z    = sig_fast(sv[64 + iA]);
            float nn   = tanh_fast(sv[192 + iA] + r * sv[128 + iA]);
            float hold = h_sh[sA0][iA];
            float hnew = nn + z * (hold - nn);
            h_sh[sA0][iA] = hnew;
            if (vA0) *hp0 = hnew;
            hp0 += dtH;
        }
        if (sA1 < SPC) {
            const float* sv = s_v[sA1];
            float r    = sig_fast(sv[iA]);
            float z    = sig_fast(sv[64 + iA]);
            float nn   = tanh_fast(sv[192 + iA] + r * sv[128 + iA]);
            float hold = h_sh[sA1][iA];
            float hnew = nn + z * (hold - nn);
            h_sh[sA1][iA] = hnew;
            if (vA1) *hp1 = hnew;
            hp1 += dtH;
        }
        __syncthreads();

#pragma unroll
        for (int s = 0; s < SPC; s++) pc[s] = pn[s];
    }
}

// ---------------- FC head ----------------
__global__ void fc_kernel(const float* __restrict__ fcw,
                          const float* __restrict__ fcb,
                          float* __restrict__ out)
{
    int g    = blockIdx.x * 8 + (threadIdx.x >> 5);
    int lane = threadIdx.x & 31;
    if (g >= MROWS) return;
    float4 v = *(const float4*)(g_hbuf + (size_t)g * 128 + lane * 4);
    float4 w = *(const float4*)(fcw + lane * 4);
    float dot = v.x * w.x + v.y * w.y + v.z * w.z + v.w * w.w;
#pragma unroll
    for (int o = 16; o > 0; o >>= 1) dot += __shfl_down_sync(0xffffffffu, dot, o);
    if (lane == 0) {
        int nidx = g / TT, t = g % TT;
        int b = nidx / 88, f = nidx % 88;
        out[((size_t)b * TT + t) * 88 + f] = sig_acc(dot + fcb[0]);
    }
}

// ---------------- launch ----------------
extern "C" void kernel_launch(void* const* d_in, const int* in_sizes, int n_in,
                              void* d_out, int out_size)
{
    const float* x    = (const float*)d_in[0];
    const float* Wih0 = (const float*)d_in[1];
    const float* Whh0 = (const float*)d_in[2];
    const float* bih0 = (const float*)d_in[3];
    const float* bhh0 = (const float*)d_in[4];
    const float* Wih1 = (const float*)d_in[5];
    const float* Whh1 = (const float*)d_in[6];
    const float* bih1 = (const float*)d_in[7];
    const float* bhh1 = (const float*)d_in[8];
    const float* fcw  = (const float*)d_in[9];
    const float* fcb  = (const float*)d_in[10];
    float* out = (float*)d_out;

    dim3 rg(NCTA_R, 2);

    proj_kernel<CDIM><<<MROWS / 256, 384>>>(x, Wih0, bih0);
    recur_kernel<<<rg, 192>>>(Whh0, bhh0);
    proj_kernel<2 * HDIM><<<MROWS / 256, 384>>>(x, Wih1, bih1);
    recur_kernel<<<rg, 192>>>(Whh1, bhh1);
    fc_kernel<<<MROWS / 8, 256>>>(fcw, fcb, out);
}